// round 16
// baseline (speedup 1.0000x reference)
#include <cuda_runtime.h>
#include <cuda_fp16.h>
#include <cstdint>
#include <cstddef>

// ---------------------------------------------------------------------------
// Problem constants: B=16, L=4096, D=H=512
// ---------------------------------------------------------------------------
constexpr int Bb   = 16;
constexpr int Lseq = 4096;
constexpr int Dm   = 512;
constexpr int Hh   = 512;
constexpr int MROWS = Bb * Lseq;          // 65536
constexpr int DFF  = 2048;                // 4*D
constexpr int NSEG = 64;
constexpr int SEGL = Lseq / NSEG;         // 64
constexpr int NCH  = Bb * Hh;             // 8192 scan chains

// ---------------------------------------------------------------------------
// Scratch (device globals)
// ---------------------------------------------------------------------------
__device__ __align__(16) __half g_Xh   [(size_t)MROWS * Dm];
__device__ __align__(16) __half g_Wsruh[(size_t)Dm * 3 * Hh];
__device__ __align__(16) __half g_W1h  [(size_t)Dm * DFF];
__device__ __align__(16) __half g_W2h  [(size_t)DFF * Dm];
__device__ __align__(16) __half g_Zh   [(size_t)MROWS * Hh];
__device__ __align__(16) __half g_Fh   [(size_t)MROWS * Hh];
__device__ __align__(16) __half g_Rh   [(size_t)MROWS * Hh];
__device__ __align__(16) __half g_X1h  [(size_t)MROWS * Dm];
__device__ __align__(16) __half g_H4h  [(size_t)MROWS * DFF];
__device__ __align__(16) __half g_X2h  [(size_t)MROWS * Dm];   // pre-LN2, fp16
__device__ __align__(16) float  g_cend [NCH * NSEG];
__device__ __align__(16) float  g_pend [NCH * NSEG];
__device__ __align__(16) float  g_carry[NCH * NSEG];

// ---------------------------------------------------------------------------
// Helpers
// ---------------------------------------------------------------------------
__device__ __forceinline__ void cp16(uint32_t dst_s, const void* src) {
    asm volatile("cp.async.cg.shared.global [%0], [%1], 16;\n" :: "r"(dst_s), "l"(src));
}
__device__ __forceinline__ void cp_commit() { asm volatile("cp.async.commit_group;\n"); }
template<int NN>
__device__ __forceinline__ void cp_wait() { asm volatile("cp.async.wait_group %0;\n" :: "n"(NN)); }

__device__ __forceinline__ void ldsm_x4(uint32_t& r0, uint32_t& r1, uint32_t& r2, uint32_t& r3,
                                        uint32_t addr) {
    asm volatile("ldmatrix.sync.aligned.m8n8.x4.shared.b16 {%0,%1,%2,%3},[%4];\n"
                 : "=r"(r0), "=r"(r1), "=r"(r2), "=r"(r3) : "r"(addr));
}
__device__ __forceinline__ void ldsm_x4t(uint32_t& r0, uint32_t& r1, uint32_t& r2, uint32_t& r3,
                                         uint32_t addr) {
    asm volatile("ldmatrix.sync.aligned.m8n8.x4.trans.shared.b16 {%0,%1,%2,%3},[%4];\n"
                 : "=r"(r0), "=r"(r1), "=r"(r2), "=r"(r3) : "r"(addr));
}
__device__ __forceinline__ void mma16(float* c, const uint32_t* a, const uint32_t* b) {
    asm volatile(
        "mma.sync.aligned.m16n8k16.row.col.f32.f16.f16.f32 "
        "{%0,%1,%2,%3},{%4,%5,%6,%7},{%8,%9},{%0,%1,%2,%3};\n"
        : "+f"(c[0]), "+f"(c[1]), "+f"(c[2]), "+f"(c[3])
        : "r"(a[0]), "r"(a[1]), "r"(a[2]), "r"(a[3]), "r"(b[0]), "r"(b[1]));
}

__device__ __forceinline__ float sigmoidf_(float v) { return 1.0f / (1.0f + expf(-v)); }
__device__ __forceinline__ float gelu_(float v) {
    return 0.5f * v * (1.0f + erff(v * 0.70710678118654752440f));
}

// ---------------------------------------------------------------------------
// fp32 -> fp16 conversions, split into two kernels for stream overlap:
//   f2h_xw : x + Wsru  (needed by GEMM1)      -> stream 0
//   f2h_w12: W1 + W2   (needed only by GEMM2) -> forked stream
// ---------------------------------------------------------------------------
constexpr int N8_X  = (MROWS * Dm) / 8;
constexpr int N8_WS = (Dm * 3 * Hh) / 8;
constexpr int N8_W1 = (Dm * DFF) / 8;
constexpr int N8_W2 = (DFF * Dm) / 8;

__device__ __forceinline__ void cvt8(const float* __restrict__ in, __half* __restrict__ out,
                                     int j) {
    const float4* src = (const float4*)in + (size_t)j * 2;
    float4 a = src[0], b = src[1];
    __half2 h[4];
    h[0] = __floats2half2_rn(a.x, a.y);
    h[1] = __floats2half2_rn(a.z, a.w);
    h[2] = __floats2half2_rn(b.x, b.y);
    h[3] = __floats2half2_rn(b.z, b.w);
    ((uint4*)out)[j] = *(uint4*)h;
}

__global__ void f2h_xw(const float* __restrict__ x, const float* __restrict__ ws) {
    int i = blockIdx.x * blockDim.x + threadIdx.x;
    if (i < N8_X)                 cvt8(x,  g_Xh,    i);
    else if (i < N8_X + N8_WS)    cvt8(ws, g_Wsruh, i - N8_X);
}

__global__ void f2h_w12(const float* __restrict__ w1, const float* __restrict__ w2) {
    int i = blockIdx.x * blockDim.x + threadIdx.x;
    if (i < N8_W1)                cvt8(w1, g_W1h, i);
    else if (i < N8_W1 + N8_W2)   cvt8(w2, g_W2h, i - N8_W1);
}

// ---------------------------------------------------------------------------
// fp16 GEMM (proven): tile 128x128x64, 3-stage cp.async, 256 thr, 2 CTA/SM,
// kt unroll x6, staged coalesced epilogues.
//   EPI=0: SRU proj -> g_Zh | g_Fh | g_Rh
//   EPI=1: MLP up   -> g_H4h = gelu(v + b1)
//   EPI=2: MLP down -> g_X2h = fp16(v + b2 + x1)  (fp32 staging, 1 rounding)
// ---------------------------------------------------------------------------
constexpr int BM = 128, BN = 128, BK = 64;
constexpr int STG_BYTES = BM * BK * 2 + BK * BN * 2;   // 32KB
constexpr int GSMEM = 3 * STG_BYTES;                    // 96KB dynamic

__device__ __forceinline__ uint32_t aoff(int r, int c) {
    return (uint32_t)(r * 128 + ((c ^ (r & 7)) << 4));
}
__device__ __forceinline__ uint32_t boff(int k, int c) {
    return (uint32_t)(k * 256 + ((c ^ (k & 7)) << 4));
}

template<int EPI, int N, int K>
__global__ __launch_bounds__(256, 2) void gemm_h(
    const float* __restrict__ bias,
    const float* __restrict__ bias2)
{
    extern __shared__ __align__(1024) char dsm[];

    const __half* __restrict__ A =
        (EPI == 0) ? g_Xh : ((EPI == 1) ? g_X1h : g_H4h);
    const __half* __restrict__ W =
        (EPI == 0) ? g_Wsruh : ((EPI == 1) ? g_W1h : g_W2h);

    const int t    = threadIdx.x;
    const int m0   = blockIdx.y * BM;
    const int n0   = blockIdx.x * BN;
    const int lane = t & 31, wid = t >> 5;
    const int gq   = lane >> 2, tg = lane & 3;
    const int wm   = (wid >> 2) * 64;
    const int wn   = (wid & 3) * 32;

    const uint32_t sBase = (uint32_t)__cvta_generic_to_shared(dsm);

    float acc[4][4][4];
    #pragma unroll
    for (int i = 0; i < 4; i++)
        #pragma unroll
        for (int j = 0; j < 4; j++)
            #pragma unroll
            for (int r = 0; r < 4; r++) acc[i][j][r] = 0.0f;

    auto loadChunk = [&](int kt, uint32_t aB) {
        const uint32_t bB = aB + BM * BK * 2;
        #pragma unroll
        for (int i = 0; i < 4; i++) {
            int idx = t + i * 256;
            int row = idx >> 3, c = idx & 7;
            cp16(aB + aoff(row, c),
                 A + (size_t)(m0 + row) * K + (size_t)kt * BK + c * 8);
        }
        #pragma unroll
        for (int i = 0; i < 4; i++) {
            int idx = t + i * 256;
            int row = idx >> 4, c = idx & 15;
            cp16(bB + boff(row, c),
                 W + (size_t)((size_t)kt * BK + row) * N + n0 + c * 8);
        }
        cp_commit();
    };

    const int KT = K / BK;
    loadChunk(0, sBase);
    if (KT > 1) loadChunk(1, sBase + STG_BYTES);

    const int ltile = lane >> 3;
    const int lrow  = lane & 7;

    uint32_t stg0 = sBase, stg1 = sBase + STG_BYTES, stg2 = sBase + 2u * STG_BYTES;

    #pragma unroll 6
    for (int kt = 0; kt < KT; ++kt) {
        if (kt + 2 <= KT) cp_wait<1>(); else cp_wait<0>();
        __syncthreads();
        if (kt + 2 < KT) loadChunk(kt + 2, stg2);

        const uint32_t aBase = stg0;
        const uint32_t bBase = stg0 + BM * BK * 2;

        #pragma unroll
        for (int ks = 0; ks < 4; ++ks) {
            uint32_t af[4][4], bf[4][2];
            #pragma unroll
            for (int mi = 0; mi < 4; mi++) {
                int row = wm + mi * 16 + ((ltile & 1) << 3) + lrow;
                int c   = ks * 2 + (ltile >> 1);
                ldsm_x4(af[mi][0], af[mi][1], af[mi][2], af[mi][3],
                        aBase + aoff(row, c));
            }
            #pragma unroll
            for (int ni2 = 0; ni2 < 2; ni2++) {
                int k = ks * 16 + ((ltile & 1) << 3) + lrow;
                int c = (wn >> 3) + ni2 * 2 + (ltile >> 1);
                uint32_t r0, r1, r2, r3;
                ldsm_x4t(r0, r1, r2, r3, bBase + boff(k, c));
                bf[ni2 * 2 + 0][0] = r0; bf[ni2 * 2 + 0][1] = r1;
                bf[ni2 * 2 + 1][0] = r2; bf[ni2 * 2 + 1][1] = r3;
            }
            #pragma unroll
            for (int mi = 0; mi < 4; mi++)
                #pragma unroll
                for (int ni = 0; ni < 4; ni++)
                    mma16(acc[mi][ni], af[mi], bf[ni]);
        }

        uint32_t tmp = stg0; stg0 = stg1; stg1 = stg2; stg2 = tmp;
    }

    // ---------------- staged epilogue (smem is dead: reuse it) --------------
    __syncthreads();

    if (EPI == 0) {
        const int seg = n0 >> 9;                 // tile fully in z|f|r region
        const int cb  = n0 - (seg << 9);
        const float* bp = (seg == 1) ? bias : bias2;
        __half* outp = (seg == 0) ? g_Zh : (seg == 1) ? g_Fh : g_Rh;
        __half* sh = (__half*)dsm;               // stride 136 halfs
        #pragma unroll
        for (int mi = 0; mi < 4; mi++)
            #pragma unroll
            for (int ni = 0; ni < 4; ni++)
                #pragma unroll
                for (int hf = 0; hf < 2; hf++) {
                    int row = wm + mi * 16 + gq + hf * 8;
                    int col = wn + ni * 8 + tg * 2;
                    float v0 = acc[mi][ni][hf * 2 + 0];
                    float v1 = acc[mi][ni][hf * 2 + 1];
                    if (seg != 0) {
                        v0 = sigmoidf_(v0 + bp[cb + col]);
                        v1 = sigmoidf_(v1 + bp[cb + col + 1]);
                    }
                    *(__half2*)(sh + row * 136 + col) = __floats2half2_rn(v0, v1);
                }
        __syncthreads();
        #pragma unroll
        for (int i = 0; i < 8; i++) {
            int idx = t + i * 256;
            int row = idx >> 4, c = idx & 15;
            uint4 v = *(uint4*)(sh + row * 136 + c * 8);
            *(uint4*)(outp + (size_t)(m0 + row) * Hh + cb + c * 8) = v;
        }
    } else if (EPI == 1) {
        __half* sh = (__half*)dsm;
        #pragma unroll
        for (int mi = 0; mi < 4; mi++)
            #pragma unroll
            for (int ni = 0; ni < 4; ni++)
                #pragma unroll
                for (int hf = 0; hf < 2; hf++) {
                    int row = wm + mi * 16 + gq + hf * 8;
                    int col = wn + ni * 8 + tg * 2;
                    float v0 = gelu_(acc[mi][ni][hf * 2 + 0] + bias[n0 + col]);
                    float v1 = gelu_(acc[mi][ni][hf * 2 + 1] + bias[n0 + col + 1]);
                    *(__half2*)(sh + row * 136 + col) = __floats2half2_rn(v0, v1);
                }
        __syncthreads();
        #pragma unroll
        for (int i = 0; i < 8; i++) {
            int idx = t + i * 256;
            int row = idx >> 4, c = idx & 15;
            uint4 v = *(uint4*)(sh + row * 136 + c * 8);
            *(uint4*)(g_H4h + (size_t)(m0 + row) * N + n0 + c * 8) = v;
        }
    } else {
        // fp32 staging; single fp16 rounding at store
        float* sf = (float*)dsm;                 // stride 132 floats
        #pragma unroll
        for (int mi = 0; mi < 4; mi++)
            #pragma unroll
            for (int ni = 0; ni < 4; ni++)
                #pragma unroll
                for (int hf = 0; hf < 2; hf++) {
                    int row = wm + mi * 16 + gq + hf * 8;
                    int col = wn + ni * 8 + tg * 2;
                    float2 v;
                    v.x = acc[mi][ni][hf * 2 + 0] + bias[n0 + col];
                    v.y = acc[mi][ni][hf * 2 + 1] + bias[n0 + col + 1];
                    *(float2*)(sf + row * 132 + col) = v;
                }
        __syncthreads();
        #pragma unroll
        for (int i = 0; i < 16; i++) {
            int idx = t + i * 256;               // 0..4095
            int row = idx >> 5, c = idx & 31;
            float4 v = *(float4*)(sf + row * 132 + c * 4);
            size_t off = (size_t)(m0 + row) * Dm + n0 + c * 4;
            uint2 xp = *(const uint2*)(g_X1h + off);
            float2 xa = __half22float2(*(__half2*)&xp.x);
            float2 xb = __half22float2(*(__half2*)&xp.y);
            __half2 h0 = __floats2half2_rn(v.x + xa.x, v.y + xa.y);
            __half2 h1 = __floats2half2_rn(v.z + xb.x, v.w + xb.y);
            uint2 pk = { *(uint32_t*)&h0, *(uint32_t*)&h1 };
            *(uint2*)(g_X2h + off) = pk;
        }
    }
}

// ---------------------------------------------------------------------------
// Segmented SRU scan, pass A: 8 chains/thread, uint4 (8xfp16) loads.
// ---------------------------------------------------------------------------
__global__ void scanA()
{
    int t = blockIdx.x * blockDim.x + threadIdx.x;   // 0 .. NCH*NSEG/8-1
    int qb = (t & (NCH / 8 - 1)) << 3;               // chain base (mult of 8)
    int s  = t >> 10;                                // NCH/8 = 1024
    int b  = qb >> 9;
    int h  = qb & (Hh - 1);
    size_t base = ((size_t)b * Lseq + (size_t)s * SEGL) * Hh + h;

    float c[8], p[8];
    #pragma unroll
    for (int j = 0; j < 8; j++) { c[j] = 0.f; p[j] = 1.f; }

    #pragma unroll 4
    for (int l = 0; l < SEGL; ++l) {
        size_t i = base + (size_t)l * Hh;
        uint4 fr = *(const uint4*)(g_Fh + i);
        uint4 zr = *(const uint4*)(g_Zh + i);
        const uint32_t* fw = (const uint32_t*)&fr;
        const uint32_t* zw = (const uint32_t*)&zr;
        #pragma unroll
        for (int v = 0; v < 4; v++) {
            float2 f2 = __half22float2(*(__half2*)&fw[v]);
            float2 z2 = __half22float2(*(__half2*)&zw[v]);
            c[v*2+0] = fmaf(f2.x, c[v*2+0] - z2.x, z2.x); p[v*2+0] *= f2.x;
            c[v*2+1] = fmaf(f2.y, c[v*2+1] - z2.y, z2.y); p[v*2+1] *= f2.y;
        }
    }
    int idx = s * NCH + qb;
    *(float4*)(g_cend + idx)     = make_float4(c[0], c[1], c[2], c[3]);
    *(float4*)(g_cend + idx + 4) = make_float4(c[4], c[5], c[6], c[7]);
    *(float4*)(g_pend + idx)     = make_float4(p[0], p[1], p[2], p[3]);
    *(float4*)(g_pend + idx + 4) = make_float4(p[4], p[5], p[6], p[7]);
}

// ---------------------------------------------------------------------------
// Pass B: carry chain with chunked prefetch (16 segs per chunk -> MLP 32).
// 128 threads x 64 blocks to spread across more SMs.
// ---------------------------------------------------------------------------
__global__ void scanB()
{
    int q = blockIdx.x * blockDim.x + threadIdx.x;   // 0..8191
    float carry = 0.0f;
    #pragma unroll
    for (int s0 = 0; s0 < NSEG; s0 += 16) {
        float ce[16], pe[16];
        #pragma unroll
        for (int j = 0; j < 16; j++) {
            int idx = (s0 + j) * NCH + q;
            ce[j] = g_cend[idx];
            pe[j] = g_pend[idx];
        }
        #pragma unroll
        for (int j = 0; j < 16; j++) {
            g_carry[(s0 + j) * NCH + q] = carry;
            carry = fmaf(pe[j], carry, ce[j]);
        }
    }
}

// ---------------------------------------------------------------------------
// Pass C fused with LayerNorm1, BATCHED: 8 timesteps per __syncthreads.
// Block = (b, seg): 256 threads x 2 chains.  Carry loaded directly.
// ---------------------------------------------------------------------------
__global__ __launch_bounds__(256) void scanC_ln(
    const float* __restrict__ gamma,
    const float* __restrict__ beta)
{
    const int blk = blockIdx.x;          // 0..Bb*NSEG-1
    const int b   = blk >> 6;
    const int s   = blk & (NSEG - 1);
    const int tid = threadIdx.x;
    const int h0  = tid << 1;
    const int lane = tid & 31, w = tid >> 5;

    const size_t base = ((size_t)b * Lseq + (size_t)s * SEGL) * Hh + h0;
    const int q = (b << 9) | h0;

    float2 cin = *(const float2*)(g_carry + s * NCH + q);
    float c0 = cin.x, c1 = cin.y;

    const float2 gg = *(const float2*)(gamma + h0);
    const float2 bb = *(const float2*)(beta  + h0);

    __shared__ float ssum[2][8][8], ssq[2][8][8];   // [buf][warp][step]

    for (int l0 = 0; l0 < SEGL; l0 += 8) {
        float hw0[8], hw1[8], ps[8], pq[8];
        #pragma unroll
        for (int j = 0; j < 8; j++) {
            size_t i = base + (size_t)(l0 + j) * Hh;
            float2 f  = __half22float2(*(const __half2*)(g_Fh + i));
            float2 z  = __half22float2(*(const __half2*)(g_Zh + i));
            float2 r  = __half22float2(*(const __half2*)(g_Rh + i));
            float2 xv = __half22float2(*(const __half2*)(g_Xh + i));
            c0 = fmaf(f.x, c0 - z.x, z.x);
            c1 = fmaf(f.y, c1 - z.y, z.y);
            hw0[j] = fmaf(r.x, c0 - xv.x, 2.0f * xv.x);
            hw1[j] = fmaf(r.y, c1 - xv.y, 2.0f * xv.y);
            ps[j] = hw0[j] + hw1[j];
            pq[j] = fmaf(hw0[j], hw0[j], hw1[j] * hw1[j]);
        }
        #pragma unroll
        for (int j = 0; j < 8; j++) {
            #pragma unroll
            for (int o = 16; o > 0; o >>= 1) {
                ps[j] += __shfl_xor_sync(0xffffffffu, ps[j], o);
                pq[j] += __shfl_xor_sync(0xffffffffu, pq[j], o);
            }
        }
        const int pb = (l0 >> 3) & 1;
        if (lane < 8) {
            ssum[pb][w][lane] = ps[lane];
            ssq [pb][w][lane] = pq[lane];
        }
        __syncthreads();
        #pragma unroll
        for (int j = 0; j < 8; j++) {
            float S = 0.f, SQ = 0.f;
            #pragma unroll
            for (int k = 0; k < 8; k++) { S += ssum[pb][k][j]; SQ += ssq[pb][k][j]; }
            const float mean = S * (1.0f / 512.0f);
            const float var  = SQ * (1.0f / 512.0f) - mean * mean;
            const float rstd = rsqrtf(var + 1e-5f);
            *(__half2*)(g_X1h + base + (size_t)(l0 + j) * Hh) = __floats2half2_rn(
                (hw0[j] - mean) * rstd * gg.x + bb.x,
                (hw1[j] - mean) * rstd * gg.y + bb.y);
        }
    }
}

// ---------------------------------------------------------------------------
// Final LayerNorm over 512: 1 block/row, 128 threads; fp16 in, fp32 out.
// ---------------------------------------------------------------------------
__global__ void ln512_out(const float* __restrict__ gamma,
                          const float* __restrict__ beta,
                          float* __restrict__ outp)
{
    size_t row = blockIdx.x;
    int t = threadIdx.x;

    uint2 pk = ((const uint2*)(g_X2h + row * Dm))[t];
    float2 va = __half22float2(*(__half2*)&pk.x);
    float2 vb = __half22float2(*(__half2*)&pk.y);

    float s  = va.x + va.y + vb.x + vb.y;
    float sq = va.x*va.x + va.y*va.y + vb.x*vb.x + vb.y*vb.y;

    #pragma unroll
    for (int o = 16; o > 0; o >>= 1) {
        s  += __shfl_xor_sync(0xffffffffu, s,  o);
        sq += __shfl_xor_sync(0xffffffffu, sq, o);
    }
    __shared__ float ssum[4], ssq[4];
    int w = t >> 5;
    if ((t & 31) == 0) { ssum[w] = s; ssq[w] = sq; }
    __syncthreads();
    float S  = ssum[0] + ssum[1] + ssum[2] + ssum[3];
    float SQ = ssq[0] + ssq[1] + ssq[2] + ssq[3];

    float mean = S * (1.0f / 512.0f);
    float var  = SQ * (1.0f / 512.0f) - mean * mean;
    float rstd = rsqrtf(var + 1e-5f);

    float4 gg = ((const float4*)gamma)[t];
    float4 bg = ((const float4*)beta)[t];
    float4 o4;
    o4.x = (va.x - mean) * rstd * gg.x + bg.x;
    o4.y = (va.y - mean) * rstd * gg.y + bg.y;
    o4.z = (vb.x - mean) * rstd * gg.z + bg.z;
    o4.w = (vb.y - mean) * rstd * gg.w + bg.w;
    ((float4*)(outp + row * Dm))[t] = o4;
}

// ---------------------------------------------------------------------------
// Launch: fork W1/W2 conversion onto a side stream so it overlaps GEMM1+scan.
// ---------------------------------------------------------------------------
extern "C" void kernel_launch(void* const* d_in, const int* in_sizes, int n_in,
                              void* d_out, int out_size)
{
    const float* x    = (const float*)d_in[0];
    const float* Wsru = (const float*)d_in[1];
    const float* b_f  = (const float*)d_in[2];
    const float* b_r  = (const float*)d_in[3];
    const float* ln1g = (const float*)d_in[4];
    const float* ln1b = (const float*)d_in[5];
    const float* W1   = (const float*)d_in[6];
    const float* b1   = (const float*)d_in[7];
    const float* W2   = (const float*)d_in[8];
    const float* b2   = (const float*)d_in[9];
    const float* ln2g = (const float*)d_in[10];
    const float* ln2b = (const float*)d_in[11];
    float* out = (float*)d_out;

    static bool init_done = false;
    static cudaStream_t s2 = nullptr;
    static cudaEvent_t evFork = nullptr, evJoin = nullptr;
    if (!init_done) {
        cudaFuncSetAttribute(gemm_h<0, 3 * Hh, Dm>,
                             cudaFuncAttributeMaxDynamicSharedMemorySize, GSMEM);
        cudaFuncSetAttribute(gemm_h<1, DFF, Dm>,
                             cudaFuncAttributeMaxDynamicSharedMemorySize, GSMEM);
        cudaFuncSetAttribute(gemm_h<2, Dm, DFF>,
                             cudaFuncAttributeMaxDynamicSharedMemorySize, GSMEM);
        cudaStreamCreateWithFlags(&s2, cudaStreamNonBlocking);
        cudaEventCreateWithFlags(&evFork, cudaEventDisableTiming);
        cudaEventCreateWithFlags(&evJoin, cudaEventDisableTiming);
        init_done = true;
    }

    // 0) x + Wsru -> fp16 (stream 0)
    {
        int n = N8_X + N8_WS;
        f2h_xw<<<(n + 255) / 256, 256>>>(x, Wsru);
    }
    // fork: W1 + W2 -> fp16 on side stream (overlaps GEMM1 + scan)
    cudaEventRecord(evFork, 0);
    cudaStreamWaitEvent(s2, evFork, 0);
    {
        int n = N8_W1 + N8_W2;
        f2h_w12<<<(n + 255) / 256, 256, 0, s2>>>(W1, W2);
    }
    cudaEventRecord(evJoin, s2);

    // 1) u = x @ W_sru, fused gate sigmoids (stream 0)
    gemm_h<0, 3 * Hh, Dm><<<dim3((3 * Hh) / BN, MROWS / BM), 256, GSMEM>>>(b_f, b_r);
    // 2) segmented recurrence pass A
    scanA<<<(NCH * NSEG / 8) / 256, 256>>>();
    // 3) carry chain (chunked prefetch, spread over 64 SMs)
    scanB<<<NCH / 128, 128>>>();
    // 4) pass C batched, fused with LN1 -> g_X1h
    scanC_ln<<<Bb * NSEG, 256>>>(ln1g, ln1b);

    // join: W1/W2 must be converted before GEMM2
    cudaStreamWaitEvent(0, evJoin, 0);

    // 5) h = gelu(x1 @ W1 + b1) -> g_H4h
    gemm_h<1, DFF, Dm><<<dim3(DFF / BN, MROWS / BM), 256, GSMEM>>>(b1, nullptr);
    // 6) x2 = fp16(x1 + h @ W2 + b2) -> g_X2h
    gemm_h<2, Dm, DFF><<<dim3(Dm / BN, MROWS / BM), 256, GSMEM>>>(b2, nullptr);
    // 7) LN2 -> d_out
    ln512_out<<<MROWS, 128>>>(ln2g, ln2b, out);
}

// round 17
// speedup vs baseline: 1.0038x; 1.0038x over previous
#include <cuda_runtime.h>
#include <cuda_fp16.h>
#include <cstdint>
#include <cstddef>

// ---------------------------------------------------------------------------
// Problem constants: B=16, L=4096, D=H=512
// ---------------------------------------------------------------------------
constexpr int Bb   = 16;
constexpr int Lseq = 4096;
constexpr int Dm   = 512;
constexpr int Hh   = 512;
constexpr int MROWS = Bb * Lseq;          // 65536
constexpr int DFF  = 2048;                // 4*D
constexpr int NSEG = 64;
constexpr int SEGL = Lseq / NSEG;         // 64
constexpr int NCH  = Bb * Hh;             // 8192 scan chains

// ---------------------------------------------------------------------------
// Scratch (device globals)
// ---------------------------------------------------------------------------
__device__ __align__(16) __half g_Xh   [(size_t)MROWS * Dm];
__device__ __align__(16) __half g_Wsruh[(size_t)Dm * 3 * Hh];
__device__ __align__(16) __half g_W1h  [(size_t)Dm * DFF];
__device__ __align__(16) __half g_W2h  [(size_t)DFF * Dm];
__device__ __align__(16) __half g_Zh   [(size_t)MROWS * Hh];
__device__ __align__(16) __half g_Fh   [(size_t)MROWS * Hh];
__device__ __align__(16) __half g_Rh   [(size_t)MROWS * Hh];
__device__ __align__(16) __half g_X1h  [(size_t)MROWS * Dm];
__device__ __align__(16) __half g_H4h  [(size_t)MROWS * DFF];
__device__ __align__(16) __half g_X2h  [(size_t)MROWS * Dm];   // pre-LN2, fp16
__device__ __align__(16) float  g_cend [NCH * NSEG];
__device__ __align__(16) float  g_pend [NCH * NSEG];
__device__ __align__(16) float  g_carry[NCH * NSEG];

// ---------------------------------------------------------------------------
// Helpers
// ---------------------------------------------------------------------------
__device__ __forceinline__ void cp16(uint32_t dst_s, const void* src) {
    asm volatile("cp.async.cg.shared.global [%0], [%1], 16;\n" :: "r"(dst_s), "l"(src));
}
__device__ __forceinline__ void cp_commit() { asm volatile("cp.async.commit_group;\n"); }
template<int NN>
__device__ __forceinline__ void cp_wait() { asm volatile("cp.async.wait_group %0;\n" :: "n"(NN)); }

__device__ __forceinline__ void ldsm_x4(uint32_t& r0, uint32_t& r1, uint32_t& r2, uint32_t& r3,
                                        uint32_t addr) {
    asm volatile("ldmatrix.sync.aligned.m8n8.x4.shared.b16 {%0,%1,%2,%3},[%4];\n"
                 : "=r"(r0), "=r"(r1), "=r"(r2), "=r"(r3) : "r"(addr));
}
__device__ __forceinline__ void ldsm_x4t(uint32_t& r0, uint32_t& r1, uint32_t& r2, uint32_t& r3,
                                         uint32_t addr) {
    asm volatile("ldmatrix.sync.aligned.m8n8.x4.trans.shared.b16 {%0,%1,%2,%3},[%4];\n"
                 : "=r"(r0), "=r"(r1), "=r"(r2), "=r"(r3) : "r"(addr));
}
__device__ __forceinline__ void mma16(float* c, const uint32_t* a, const uint32_t* b) {
    asm volatile(
        "mma.sync.aligned.m16n8k16.row.col.f32.f16.f16.f32 "
        "{%0,%1,%2,%3},{%4,%5,%6,%7},{%8,%9},{%0,%1,%2,%3};\n"
        : "+f"(c[0]), "+f"(c[1]), "+f"(c[2]), "+f"(c[3])
        : "r"(a[0]), "r"(a[1]), "r"(a[2]), "r"(a[3]), "r"(b[0]), "r"(b[1]));
}

__device__ __forceinline__ float sigmoidf_(float v) { return 1.0f / (1.0f + expf(-v)); }
__device__ __forceinline__ float gelu_(float v) {
    return 0.5f * v * (1.0f + erff(v * 0.70710678118654752440f));
}

// ---------------------------------------------------------------------------
// fp32 -> fp16, all four arrays in one launch
// ---------------------------------------------------------------------------
constexpr int N8_X  = (MROWS * Dm) / 8;
constexpr int N8_WS = (Dm * 3 * Hh) / 8;
constexpr int N8_W1 = (Dm * DFF) / 8;
constexpr int N8_W2 = (DFF * Dm) / 8;
constexpr int N8_TOT = N8_X + N8_WS + N8_W1 + N8_W2;

__device__ __forceinline__ void cvt8(const float* __restrict__ in, __half* __restrict__ out,
                                     int j) {
    const float4* src = (const float4*)in + (size_t)j * 2;
    float4 a = src[0], b = src[1];
    __half2 h[4];
    h[0] = __floats2half2_rn(a.x, a.y);
    h[1] = __floats2half2_rn(a.z, a.w);
    h[2] = __floats2half2_rn(b.x, b.y);
    h[3] = __floats2half2_rn(b.z, b.w);
    ((uint4*)out)[j] = *(uint4*)h;
}

__global__ void f2h_all(const float* __restrict__ x,  const float* __restrict__ ws,
                        const float* __restrict__ w1, const float* __restrict__ w2) {
    int i = blockIdx.x * blockDim.x + threadIdx.x;
    if (i < N8_X)                      cvt8(x,  g_Xh,    i);
    else if (i < N8_X + N8_WS)         cvt8(ws, g_Wsruh, i - N8_X);
    else if (i < N8_X + N8_WS + N8_W1) cvt8(w1, g_W1h,   i - N8_X - N8_WS);
    else if (i < N8_TOT)               cvt8(w2, g_W2h,   i - N8_X - N8_WS - N8_W1);
}

// ---------------------------------------------------------------------------
// fp16 GEMM (proven): tile 128x128x64, 3-stage cp.async, 256 thr, 2 CTA/SM,
// kt unroll x6, staged coalesced epilogues.
//   EPI=0: SRU proj -> g_Zh | g_Fh | g_Rh
//   EPI=1: MLP up   -> g_H4h = gelu(v + b1)
//   EPI=2: MLP down -> g_X2h = fp16(v + b2 + x1)  (fp32 staging, 1 rounding)
// ---------------------------------------------------------------------------
constexpr int BM = 128, BN = 128, BK = 64;
constexpr int STG_BYTES = BM * BK * 2 + BK * BN * 2;   // 32KB
constexpr int GSMEM = 3 * STG_BYTES;                    // 96KB dynamic

__device__ __forceinline__ uint32_t aoff(int r, int c) {
    return (uint32_t)(r * 128 + ((c ^ (r & 7)) << 4));
}
__device__ __forceinline__ uint32_t boff(int k, int c) {
    return (uint32_t)(k * 256 + ((c ^ (k & 7)) << 4));
}

template<int EPI, int N, int K>
__global__ __launch_bounds__(256, 2) void gemm_h(
    const float* __restrict__ bias,
    const float* __restrict__ bias2)
{
    extern __shared__ __align__(1024) char dsm[];

    const __half* __restrict__ A =
        (EPI == 0) ? g_Xh : ((EPI == 1) ? g_X1h : g_H4h);
    const __half* __restrict__ W =
        (EPI == 0) ? g_Wsruh : ((EPI == 1) ? g_W1h : g_W2h);

    const int t    = threadIdx.x;
    const int m0   = blockIdx.y * BM;
    const int n0   = blockIdx.x * BN;
    const int lane = t & 31, wid = t >> 5;
    const int gq   = lane >> 2, tg = lane & 3;
    const int wm   = (wid >> 2) * 64;
    const int wn   = (wid & 3) * 32;

    const uint32_t sBase = (uint32_t)__cvta_generic_to_shared(dsm);

    float acc[4][4][4];
    #pragma unroll
    for (int i = 0; i < 4; i++)
        #pragma unroll
        for (int j = 0; j < 4; j++)
            #pragma unroll
            for (int r = 0; r < 4; r++) acc[i][j][r] = 0.0f;

    auto loadChunk = [&](int kt, uint32_t aB) {
        const uint32_t bB = aB + BM * BK * 2;
        #pragma unroll
        for (int i = 0; i < 4; i++) {
            int idx = t + i * 256;
            int row = idx >> 3, c = idx & 7;
            cp16(aB + aoff(row, c),
                 A + (size_t)(m0 + row) * K + (size_t)kt * BK + c * 8);
        }
        #pragma unroll
        for (int i = 0; i < 4; i++) {
            int idx = t + i * 256;
            int row = idx >> 4, c = idx & 15;
            cp16(bB + boff(row, c),
                 W + (size_t)((size_t)kt * BK + row) * N + n0 + c * 8);
        }
        cp_commit();
    };

    const int KT = K / BK;
    loadChunk(0, sBase);
    if (KT > 1) loadChunk(1, sBase + STG_BYTES);

    const int ltile = lane >> 3;
    const int lrow  = lane & 7;

    uint32_t stg0 = sBase, stg1 = sBase + STG_BYTES, stg2 = sBase + 2u * STG_BYTES;

    #pragma unroll 6
    for (int kt = 0; kt < KT; ++kt) {
        if (kt + 2 <= KT) cp_wait<1>(); else cp_wait<0>();
        __syncthreads();
        if (kt + 2 < KT) loadChunk(kt + 2, stg2);

        const uint32_t aBase = stg0;
        const uint32_t bBase = stg0 + BM * BK * 2;

        #pragma unroll
        for (int ks = 0; ks < 4; ++ks) {
            uint32_t af[4][4], bf[4][2];
            #pragma unroll
            for (int mi = 0; mi < 4; mi++) {
                int row = wm + mi * 16 + ((ltile & 1) << 3) + lrow;
                int c   = ks * 2 + (ltile >> 1);
                ldsm_x4(af[mi][0], af[mi][1], af[mi][2], af[mi][3],
                        aBase + aoff(row, c));
            }
            #pragma unroll
            for (int ni2 = 0; ni2 < 2; ni2++) {
                int k = ks * 16 + ((ltile & 1) << 3) + lrow;
                int c = (wn >> 3) + ni2 * 2 + (ltile >> 1);
                uint32_t r0, r1, r2, r3;
                ldsm_x4t(r0, r1, r2, r3, bBase + boff(k, c));
                bf[ni2 * 2 + 0][0] = r0; bf[ni2 * 2 + 0][1] = r1;
                bf[ni2 * 2 + 1][0] = r2; bf[ni2 * 2 + 1][1] = r3;
            }
            #pragma unroll
            for (int mi = 0; mi < 4; mi++)
                #pragma unroll
                for (int ni = 0; ni < 4; ni++)
                    mma16(acc[mi][ni], af[mi], bf[ni]);
        }

        uint32_t tmp = stg0; stg0 = stg1; stg1 = stg2; stg2 = tmp;
    }

    // ---------------- staged epilogue (smem is dead: reuse it) --------------
    __syncthreads();

    if (EPI == 0) {
        const int seg = n0 >> 9;                 // tile fully in z|f|r region
        const int cb  = n0 - (seg << 9);
        const float* bp = (seg == 1) ? bias : bias2;
        __half* outp = (seg == 0) ? g_Zh : (seg == 1) ? g_Fh : g_Rh;
        __half* sh = (__half*)dsm;               // stride 136 halfs
        #pragma unroll
        for (int mi = 0; mi < 4; mi++)
            #pragma unroll
            for (int ni = 0; ni < 4; ni++)
                #pragma unroll
                for (int hf = 0; hf < 2; hf++) {
                    int row = wm + mi * 16 + gq + hf * 8;
                    int col = wn + ni * 8 + tg * 2;
                    float v0 = acc[mi][ni][hf * 2 + 0];
                    float v1 = acc[mi][ni][hf * 2 + 1];
                    if (seg != 0) {
                        v0 = sigmoidf_(v0 + bp[cb + col]);
                        v1 = sigmoidf_(v1 + bp[cb + col + 1]);
                    }
                    *(__half2*)(sh + row * 136 + col) = __floats2half2_rn(v0, v1);
                }
        __syncthreads();
        #pragma unroll
        for (int i = 0; i < 8; i++) {
            int idx = t + i * 256;
            int row = idx >> 4, c = idx & 15;
            uint4 v = *(uint4*)(sh + row * 136 + c * 8);
            *(uint4*)(outp + (size_t)(m0 + row) * Hh + cb + c * 8) = v;
        }
    } else if (EPI == 1) {
        __half* sh = (__half*)dsm;
        #pragma unroll
        for (int mi = 0; mi < 4; mi++)
            #pragma unroll
            for (int ni = 0; ni < 4; ni++)
                #pragma unroll
                for (int hf = 0; hf < 2; hf++) {
                    int row = wm + mi * 16 + gq + hf * 8;
                    int col = wn + ni * 8 + tg * 2;
                    float v0 = gelu_(acc[mi][ni][hf * 2 + 0] + bias[n0 + col]);
                    float v1 = gelu_(acc[mi][ni][hf * 2 + 1] + bias[n0 + col + 1]);
                    *(__half2*)(sh + row * 136 + col) = __floats2half2_rn(v0, v1);
                }
        __syncthreads();
        #pragma unroll
        for (int i = 0; i < 8; i++) {
            int idx = t + i * 256;
            int row = idx >> 4, c = idx & 15;
            uint4 v = *(uint4*)(sh + row * 136 + c * 8);
            *(uint4*)(g_H4h + (size_t)(m0 + row) * N + n0 + c * 8) = v;
        }
    } else {
        // fp32 staging; single fp16 rounding at store
        float* sf = (float*)dsm;                 // stride 132 floats
        #pragma unroll
        for (int mi = 0; mi < 4; mi++)
            #pragma unroll
            for (int ni = 0; ni < 4; ni++)
                #pragma unroll
                for (int hf = 0; hf < 2; hf++) {
                    int row = wm + mi * 16 + gq + hf * 8;
                    int col = wn + ni * 8 + tg * 2;
                    float2 v;
                    v.x = acc[mi][ni][hf * 2 + 0] + bias[n0 + col];
                    v.y = acc[mi][ni][hf * 2 + 1] + bias[n0 + col + 1];
                    *(float2*)(sf + row * 132 + col) = v;
                }
        __syncthreads();
        #pragma unroll
        for (int i = 0; i < 16; i++) {
            int idx = t + i * 256;               // 0..4095
            int row = idx >> 5, c = idx & 31;
            float4 v = *(float4*)(sf + row * 132 + c * 4);
            size_t off = (size_t)(m0 + row) * Dm + n0 + c * 4;
            uint2 xp = *(const uint2*)(g_X1h + off);
            float2 xa = __half22float2(*(__half2*)&xp.x);
            float2 xb = __half22float2(*(__half2*)&xp.y);
            __half2 h0 = __floats2half2_rn(v.x + xa.x, v.y + xa.y);
            __half2 h1 = __floats2half2_rn(v.z + xb.x, v.w + xb.y);
            uint2 pk = { *(uint32_t*)&h0, *(uint32_t*)&h1 };
            *(uint2*)(g_X2h + off) = pk;
        }
    }
}

// ---------------------------------------------------------------------------
// Segmented SRU scan, pass A: 4 chains/thread, uint2 (4xfp16) loads.
// grid = NCH*NSEG/4/256 = 512 blocks -> ~3.5 CTA/SM for DRAM-queue depth.
// ---------------------------------------------------------------------------
__global__ void scanA()
{
    int t = blockIdx.x * blockDim.x + threadIdx.x;   // 0 .. NCH*NSEG/4-1
    int qb = (t & (NCH / 4 - 1)) << 2;               // chain base (mult of 4)
    int s  = t >> 11;                                // NCH/4 = 2048
    int b  = qb >> 9;
    int h  = qb & (Hh - 1);
    size_t base = ((size_t)b * Lseq + (size_t)s * SEGL) * Hh + h;

    float c0 = 0.f, c1 = 0.f, c2 = 0.f, c3 = 0.f;
    float p0 = 1.f, p1 = 1.f, p2 = 1.f, p3 = 1.f;
    #pragma unroll 8
    for (int l = 0; l < SEGL; ++l) {
        size_t i = base + (size_t)l * Hh;
        uint2 fr = *(const uint2*)(g_Fh + i);
        uint2 zr = *(const uint2*)(g_Zh + i);
        float2 fa = __half22float2(*(__half2*)&fr.x);
        float2 fb = __half22float2(*(__half2*)&fr.y);
        float2 za = __half22float2(*(__half2*)&zr.x);
        float2 zb = __half22float2(*(__half2*)&zr.y);
        c0 = fmaf(fa.x, c0 - za.x, za.x); p0 *= fa.x;
        c1 = fmaf(fa.y, c1 - za.y, za.y); p1 *= fa.y;
        c2 = fmaf(fb.x, c2 - zb.x, zb.x); p2 *= fb.x;
        c3 = fmaf(fb.y, c3 - zb.y, zb.y); p3 *= fb.y;
    }
    int idx = s * NCH + qb;
    *(float4*)(g_cend + idx) = make_float4(c0, c1, c2, c3);
    *(float4*)(g_pend + idx) = make_float4(p0, p1, p2, p3);
}

// ---------------------------------------------------------------------------
// Pass B: carry chain with chunked prefetch (16 segs per chunk -> MLP 32).
// 128 threads x 64 blocks to spread across more SMs.
// ---------------------------------------------------------------------------
__global__ void scanB()
{
    int q = blockIdx.x * blockDim.x + threadIdx.x;   // 0..8191
    float carry = 0.0f;
    #pragma unroll
    for (int s0 = 0; s0 < NSEG; s0 += 16) {
        float ce[16], pe[16];
        #pragma unroll
        for (int j = 0; j < 16; j++) {
            int idx = (s0 + j) * NCH + q;
            ce[j] = g_cend[idx];
            pe[j] = g_pend[idx];
        }
        #pragma unroll
        for (int j = 0; j < 16; j++) {
            g_carry[(s0 + j) * NCH + q] = carry;
            carry = fmaf(pe[j], carry, ce[j]);
        }
    }
}

// ---------------------------------------------------------------------------
// Pass C fused with LayerNorm1, BATCHED: 8 timesteps per __syncthreads.
// Block = (b, seg): 256 threads x 2 chains.  Carry loaded directly.
// ---------------------------------------------------------------------------
__global__ __launch_bounds__(256) void scanC_ln(
    const float* __restrict__ gamma,
    const float* __restrict__ beta)
{
    const int blk = blockIdx.x;          // 0..Bb*NSEG-1
    const int b   = blk >> 6;
    const int s   = blk & (NSEG - 1);
    const int tid = threadIdx.x;
    const int h0  = tid << 1;
    const int lane = tid & 31, w = tid >> 5;

    const size_t base = ((size_t)b * Lseq + (size_t)s * SEGL) * Hh + h0;
    const int q = (b << 9) | h0;

    float2 cin = *(const float2*)(g_carry + s * NCH + q);
    float c0 = cin.x, c1 = cin.y;

    const float2 gg = *(const float2*)(gamma + h0);
    const float2 bb = *(const float2*)(beta  + h0);

    __shared__ float ssum[2][8][8], ssq[2][8][8];   // [buf][warp][step]

    for (int l0 = 0; l0 < SEGL; l0 += 8) {
        float hw0[8], hw1[8], ps[8], pq[8];
        #pragma unroll
        for (int j = 0; j < 8; j++) {
            size_t i = base + (size_t)(l0 + j) * Hh;
            float2 f  = __half22float2(*(const __half2*)(g_Fh + i));
            float2 z  = __half22float2(*(const __half2*)(g_Zh + i));
            float2 r  = __half22float2(*(const __half2*)(g_Rh + i));
            float2 xv = __half22float2(*(const __half2*)(g_Xh + i));
            c0 = fmaf(f.x, c0 - z.x, z.x);
            c1 = fmaf(f.y, c1 - z.y, z.y);
            hw0[j] = fmaf(r.x, c0 - xv.x, 2.0f * xv.x);
            hw1[j] = fmaf(r.y, c1 - xv.y, 2.0f * xv.y);
            ps[j] = hw0[j] + hw1[j];
            pq[j] = fmaf(hw0[j], hw0[j], hw1[j] * hw1[j]);
        }
        #pragma unroll
        for (int j = 0; j < 8; j++) {
            #pragma unroll
            for (int o = 16; o > 0; o >>= 1) {
                ps[j] += __shfl_xor_sync(0xffffffffu, ps[j], o);
                pq[j] += __shfl_xor_sync(0xffffffffu, pq[j], o);
            }
        }
        const int pb = (l0 >> 3) & 1;
        if (lane < 8) {
            ssum[pb][w][lane] = ps[lane];
            ssq [pb][w][lane] = pq[lane];
        }
        __syncthreads();
        #pragma unroll
        for (int j = 0; j < 8; j++) {
            float S = 0.f, SQ = 0.f;
            #pragma unroll
            for (int k = 0; k < 8; k++) { S += ssum[pb][k][j]; SQ += ssq[pb][k][j]; }
            const float mean = S * (1.0f / 512.0f);
            const float var  = SQ * (1.0f / 512.0f) - mean * mean;
            const float rstd = rsqrtf(var + 1e-5f);
            *(__half2*)(g_X1h + base + (size_t)(l0 + j) * Hh) = __floats2half2_rn(
                (hw0[j] - mean) * rstd * gg.x + bb.x,
                (hw1[j] - mean) * rstd * gg.y + bb.y);
        }
    }
}

// ---------------------------------------------------------------------------
// Final LayerNorm over 512: 1 block/row, 128 threads; fp16 in, fp32 out.
// ---------------------------------------------------------------------------
__global__ void ln512_out(const float* __restrict__ gamma,
                          const float* __restrict__ beta,
                          float* __restrict__ outp)
{
    size_t row = blockIdx.x;
    int t = threadIdx.x;

    uint2 pk = ((const uint2*)(g_X2h + row * Dm))[t];
    float2 va = __half22float2(*(__half2*)&pk.x);
    float2 vb = __half22float2(*(__half2*)&pk.y);

    float s  = va.x + va.y + vb.x + vb.y;
    float sq = va.x*va.x + va.y*va.y + vb.x*vb.x + vb.y*vb.y;

    #pragma unroll
    for (int o = 16; o > 0; o >>= 1) {
        s  += __shfl_xor_sync(0xffffffffu, s,  o);
        sq += __shfl_xor_sync(0xffffffffu, sq, o);
    }
    __shared__ float ssum[4], ssq[4];
    int w = t >> 5;
    if ((t & 31) == 0) { ssum[w] = s; ssq[w] = sq; }
    __syncthreads();
    float S  = ssum[0] + ssum[1] + ssum[2] + ssum[3];
    float SQ = ssq[0] + ssq[1] + ssq[2] + ssq[3];

    float mean = S * (1.0f / 512.0f);
    float var  = SQ * (1.0f / 512.0f) - mean * mean;
    float rstd = rsqrtf(var + 1e-5f);

    float4 gg = ((const float4*)gamma)[t];
    float4 bg = ((const float4*)beta)[t];
    float4 o4;
    o4.x = (va.x - mean) * rstd * gg.x + bg.x;
    o4.y = (va.y - mean) * rstd * gg.y + bg.y;
    o4.z = (vb.x - mean) * rstd * gg.z + bg.z;
    o4.w = (vb.y - mean) * rstd * gg.w + bg.w;
    ((float4*)(outp + row * Dm))[t] = o4;
}

// ---------------------------------------------------------------------------
// Launch (linear, single stream — R15-proven ordering)
// ---------------------------------------------------------------------------
extern "C" void kernel_launch(void* const* d_in, const int* in_sizes, int n_in,
                              void* d_out, int out_size)
{
    const float* x    = (const float*)d_in[0];
    const float* Wsru = (const float*)d_in[1];
    const float* b_f  = (const float*)d_in[2];
    const float* b_r  = (const float*)d_in[3];
    const float* ln1g = (const float*)d_in[4];
    const float* ln1b = (const float*)d_in[5];
    const float* W1   = (const float*)d_in[6];
    const float* b1   = (const float*)d_in[7];
    const float* W2   = (const float*)d_in[8];
    const float* b2   = (const float*)d_in[9];
    const float* ln2g = (const float*)d_in[10];
    const float* ln2b = (const float*)d_in[11];
    float* out = (float*)d_out;

    static bool attr_done = false;
    if (!attr_done) {
        cudaFuncSetAttribute(gemm_h<0, 3 * Hh, Dm>,
                             cudaFuncAttributeMaxDynamicSharedMemorySize, GSMEM);
        cudaFuncSetAttribute(gemm_h<1, DFF, Dm>,
                             cudaFuncAttributeMaxDynamicSharedMemorySize, GSMEM);
        cudaFuncSetAttribute(gemm_h<2, Dm, DFF>,
                             cudaFuncAttributeMaxDynamicSharedMemorySize, GSMEM);
        attr_done = true;
    }

    // 0) all fp32 -> fp16 conversions
    f2h_all<<<(N8_TOT + 255) / 256, 256>>>(x, Wsru, W1, W2);
    // 1) u = x @ W_sru, fused gate sigmoids
    gemm_h<0, 3 * Hh, Dm><<<dim3((3 * Hh) / BN, MROWS / BM), 256, GSMEM>>>(b_f, b_r);
    // 2) segmented recurrence pass A (4 chains/thread, 512 blocks)
    scanA<<<(NCH * NSEG / 4) / 256, 256>>>();
    // 3) carry chain (chunked prefetch, spread over 64 SMs)
    scanB<<<NCH / 128, 128>>>();
    // 4) pass C batched, fused with LN1 -> g_X1h
    scanC_ln<<<Bb * NSEG, 256>>>(ln1g, ln1b);
    // 5) h = gelu(x1 @ W1 + b1) -> g_H4h
    gemm_h<1, DFF, Dm><<<dim3(DFF / BN, MROWS / BM), 256, GSMEM>>>(b1, nullptr);
    // 6) x2 = fp16(x1 + h @ W2 + b2) -> g_X2h
    gemm_h<2, Dm, DFF><<<dim3(Dm / BN, MROWS / BM), 256, GSMEM>>>(b2, nullptr);
    // 7) LN2 -> d_out
    ln512_out<<<MROWS, 128>>>(ln2g, ln2b, out);
}